// round 12
// baseline (speedup 1.0000x reference)
#include <cuda_runtime.h>
#include <stdint.h>

#define NGMAX    (1 << 20)       // >= n_groups
#define LISTMAX  (1 << 25)       // deferred-element index list
#define NBLK_MAX 65536
#define BGFMAX   (1 << 22)       // fallback boundary-group list
#define BLOCK    256
#define EPT      8
#define TILE     (BLOCK * EPT)   // 2048
#define TABLE    768             // group-id span per tile (expected ~102)

__device__ float              g_denom[NGMAX];      // boundary groups: sum of exp(s)
__device__ unsigned long long g_snpack[NGMAX];     // boundary groups: (sn_bits<<32)|idx
__device__ unsigned g_ndef;                        // deferred element count (k_fused only)
__device__ int      g_list[LISTMAX];               // deferred element indices
__device__ int      g_bg[2 * NBLK_MAX];            // fixed slots: 2 per tile, -1 = empty
__device__ unsigned g_nbgf;                        // fallback group count (k_fused only)
__device__ int      g_bgf[BGFMAX];                 // fallback group ids

#define INV_T     (1.0f / 0.6f)
#define EPS_NOISE 1e-4f

// exp((logit + gumbel)/T), no max-shift needed: s in [-14, 33] -> no fp32 overflow.
// Inner log must stay accurate (u near 1 -> -log(u) near 0); outer log/exp fast.
__device__ __forceinline__ float gumbel_e(float l, float u) {
    float y = -logf(u);
    return __expf((l - __logf(y)) * INV_T);
}

// One thread per tile. No racing counters: boundary groups -> fixed slots.
__global__ __launch_bounds__(128) void k_init(const int* __restrict__ grp,
                                              int E, int nblocks)
{
    int b = blockIdx.x * 128 + threadIdx.x;
    if (b == 0) { g_ndef = 0u; g_nbgf = 0u; }
    if (b >= nblocks) return;
    int base0 = b * TILE;
    int tile_n = min(TILE, E - base0);
    int g0 = grp[base0];
    int glast = grp[base0 + tile_n - 1];
    int gprev = (base0 > 0) ? grp[base0 - 1] : -1;
    int gnext = (base0 + tile_n < E) ? grp[base0 + tile_n] : -1;
    bool g0_b = (gprev == g0);
    bool gl_b = (gnext == glast);
    if (g0 == glast) { bool any = g0_b || gl_b; g0_b = any; gl_b = any; }

    g_denom[g0] = 0.0f;    g_snpack[g0] = 0ull;
    g_denom[glast] = 0.0f; g_snpack[glast] = 0ull;

    if (glast - g0 >= TABLE) {  // pathological fallback tile: zero whole span
        for (int g = g0 + 1; g < glast; g++) { g_denom[g] = 0.0f; g_snpack[g] = 0ull; }
        g_bg[2 * b]     = -1;
        g_bg[2 * b + 1] = -1;
        return;
    }
    g_bg[2 * b]     = g0_b ? g0 : -1;
    g_bg[2 * b + 1] = (gl_b && glast != g0) ? glast : -1;
}

__global__ __launch_bounds__(BLOCK) void k_fused(
    const float* __restrict__ logits, const float* __restrict__ ug,
    const float* __restrict__ ue, const int* __restrict__ grp,
    float* __restrict__ out_soft, float* __restrict__ out_st,
    float* __restrict__ out_hot, int E)
{
    __shared__ float    s_sum[TABLE];
    __shared__ unsigned s_max[TABLE];
    __shared__ int sh[4];  // g0, glast, gprev, gnext

    const int b      = blockIdx.x;
    const int base0  = b * TILE;
    const int tid    = threadIdx.x;
    const int tile_n = min(TILE, E - base0);

    // Merged front barrier: tid0 fetches edges while all threads zero the table.
    if (tid == 0) {
        sh[0] = grp[base0];
        sh[1] = grp[base0 + tile_n - 1];
        sh[2] = (base0 > 0) ? grp[base0 - 1] : -1;
        sh[3] = (base0 + tile_n < E) ? grp[base0 + tile_n] : -1;
    }
#pragma unroll
    for (int i = tid; i < TABLE; i += BLOCK) { s_sum[i] = 0.0f; s_max[i] = 0u; }
    __syncthreads();

    const int g0    = sh[0];
    const int glast = sh[1];
    const int span  = glast - g0;
    const bool fallback = (span >= TABLE);
    bool g0_b = (sh[2] == g0);
    bool gl_b = (sh[3] == glast);
    if (g0 == glast) { bool any = g0_b || gl_b; g0_b = any; gl_b = any; }

    const int base = base0 + tid * EPT;
    const int cnt  = max(0, min(EPT, E - base));

    float e[EPT];
    int g[EPT];

    // Phase A: load logits/ug/grp only; compute e; l,u die immediately.
    if (cnt == EPT) {
        float4 L0 = __ldcs(reinterpret_cast<const float4*>(logits + base));
        float4 L1 = __ldcs(reinterpret_cast<const float4*>(logits + base) + 1);
        float4 U0 = __ldcs(reinterpret_cast<const float4*>(ug + base));
        float4 U1 = __ldcs(reinterpret_cast<const float4*>(ug + base) + 1);
        int4   G0 = __ldcs(reinterpret_cast<const int4*>(grp + base));
        int4   G1 = __ldcs(reinterpret_cast<const int4*>(grp + base) + 1);
        g[0]=G0.x;g[1]=G0.y;g[2]=G0.z;g[3]=G0.w;g[4]=G1.x;g[5]=G1.y;g[6]=G1.z;g[7]=G1.w;
        e[0]=gumbel_e(L0.x,U0.x); e[1]=gumbel_e(L0.y,U0.y);
        e[2]=gumbel_e(L0.z,U0.z); e[3]=gumbel_e(L0.w,U0.w);
        e[4]=gumbel_e(L1.x,U1.x); e[5]=gumbel_e(L1.y,U1.y);
        e[6]=gumbel_e(L1.z,U1.z); e[7]=gumbel_e(L1.w,U1.w);
    } else {
        for (int j = 0; j < cnt; j++) {
            e[j] = gumbel_e(logits[base+j], ug[base+j]);
            g[j] = grp[base+j];
        }
    }

    // Interior segment sums into smem (pre-PDL-sync: touches no global state).
    if (!fallback && cnt > 0) {
        float acc = e[0]; int cg = g[0];
        for (int j = 1; j < cnt; j++) {
            if (g[j] == cg) acc += e[j];
            else { atomicAdd(&s_sum[cg - g0], acc); cg = g[j]; acc = e[j]; }
        }
        atomicAdd(&s_sum[cg - g0], acc);
    }

    // PDL: wait for k_init's zeroing/counter reset before touching globals.
    cudaGridDependencySynchronize();

    if (fallback && cnt > 0) {  // global run-aggregated sums
        float acc = e[0]; int cg = g[0];
        for (int j = 1; j < cnt; j++) {
            if (g[j] == cg) acc += e[j];
            else { atomicAdd(&g_denom[cg], acc); cg = g[j]; acc = e[j]; }
        }
        atomicAdd(&g_denom[cg], acc);
    }

    // Deferred (boundary / fallback) elements -> element index list.
    bool def[EPT];
#pragma unroll
    for (int j = 0; j < EPT; j++) {
        def[j] = (j < cnt) &&
                 (fallback || (g[j] == g0 && g0_b) || (g[j] == glast && gl_b));
    }
    {
        int nd = 0; int didx[EPT];
#pragma unroll
        for (int j = 0; j < EPT; j++)
            if (def[j]) didx[nd++] = base + j;
        if (nd) {
            unsigned p = atomicAdd(&g_ndef, (unsigned)nd);
            for (int i = 0; i < nd; i++) g_list[p + i] = didx[i];
        }
    }

    if (fallback) {
        if (tid == 0) {
            unsigned p = atomicAdd(&g_nbgf, (unsigned)(span + 1));
            for (int gg = g0; gg <= glast; gg++) g_bgf[p++] = gg;
        }
        if (cnt == EPT) {
            __stcs(reinterpret_cast<float4*>(out_soft + base),
                   make_float4(e[0],e[1],e[2],e[3]));
            __stcs(reinterpret_cast<float4*>(out_soft + base) + 1,
                   make_float4(e[4],e[5],e[6],e[7]));
            float4 z = make_float4(0.f,0.f,0.f,0.f);
            __stcs(reinterpret_cast<float4*>(out_st + base), z);
            __stcs(reinterpret_cast<float4*>(out_st + base) + 1, z);
            __stcs(reinterpret_cast<float4*>(out_hot + base), z);
            __stcs(reinterpret_cast<float4*>(out_hot + base) + 1, z);
        } else {
            for (int j = 0; j < cnt; j++) {
                out_soft[base + j] = e[j];
                out_st[base + j] = 0.f; out_hot[base + j] = 0.f;
            }
        }
        return;
    }

    // Prefetch ue BEFORE the barrier: its latency drains during the sync wait.
    float n[EPT];
    if (cnt == EPT) {
        float4 N0 = __ldcs(reinterpret_cast<const float4*>(ue + base));
        float4 N1 = __ldcs(reinterpret_cast<const float4*>(ue + base) + 1);
        n[0]=N0.x;n[1]=N0.y;n[2]=N0.z;n[3]=N0.w;
        n[4]=N1.x;n[5]=N1.y;n[6]=N1.z;n[7]=N1.w;
    } else {
        for (int j = 0; j < cnt; j++) n[j] = ue[base + j];
    }
    __syncthreads();

    if (tid == 0) {
        if (g0_b)                atomicAdd(&g_denom[g0],    s_sum[0]);
        if (gl_b && glast != g0) atomicAdd(&g_denom[glast], s_sum[span]);
    }

    // Phase B: soft (one reciprocal per run), write out_soft immediately
    // (deferred slots stash e for fixup); smem argmax for interior.
    unsigned snb[EPT];
    if (cnt > 0) {
        float val[EPT];
        int cg = g[0];
        float rdn = 1.0f / s_sum[cg - g0];
#pragma unroll
        for (int j = 0; j < EPT; j++) {
            if (j < cnt) {
                if (g[j] != cg) { cg = g[j]; rdn = 1.0f / s_sum[cg - g0]; }
                float soft = e[j] * rdn;
                snb[j] = __float_as_uint(__fmaf_rn(EPS_NOISE, n[j], soft));
                val[j] = def[j] ? e[j] : soft;
            }
        }
        if (cnt == EPT) {
            __stcs(reinterpret_cast<float4*>(out_soft + base),
                   make_float4(val[0],val[1],val[2],val[3]));
            __stcs(reinterpret_cast<float4*>(out_soft + base) + 1,
                   make_float4(val[4],val[5],val[6],val[7]));
        } else {
            for (int j = 0; j < cnt; j++) out_soft[base + j] = val[j];
        }
        unsigned m = 0; int cg2 = -1;
        for (int j = 0; j < cnt; j++) {
            if (def[j]) continue;
            if (g[j] == cg2) { if (snb[j] > m) m = snb[j]; }
            else {
                if (cg2 >= 0) atomicMax(&s_max[cg2 - g0], m);
                cg2 = g[j]; m = snb[j];
            }
        }
        if (cg2 >= 0) atomicMax(&s_max[cg2 - g0], m);
    }
    __syncthreads();

    // Final phase: h (def slots 0; scatter writes winners), write st/hot.
    if (cnt > 0) {
        float h[EPT];
#pragma unroll
        for (int j = 0; j < EPT; j++) {
            if (j < cnt)
                h[j] = (!def[j] && snb[j] == s_max[g[j] - g0]) ? 1.0f : 0.0f;
        }
        if (cnt == EPT) {
            __stcs(reinterpret_cast<float4*>(out_st + base),
                   make_float4(h[0],h[1],h[2],h[3]));
            __stcs(reinterpret_cast<float4*>(out_st + base) + 1,
                   make_float4(h[4],h[5],h[6],h[7]));
            __stcs(reinterpret_cast<float4*>(out_hot + base),
                   make_float4(h[0],h[1],h[2],h[3]));
            __stcs(reinterpret_cast<float4*>(out_hot + base) + 1,
                   make_float4(h[4],h[5],h[6],h[7]));
        } else {
            for (int j = 0; j < cnt; j++) {
                out_st[base + j]  = h[j];
                out_hot[base + j] = h[j];
            }
        }
    }
}

// Fixup A: per deferred element — e stashed in out_soft; finalize soft + argmax.
__global__ __launch_bounds__(256) void k_fix_max(
    const float* __restrict__ ue, const int* __restrict__ grp,
    float* __restrict__ out_soft)
{
    cudaGridDependencySynchronize();
    unsigned count = g_ndef;
    unsigned stride = gridDim.x * 256;
    for (unsigned i = blockIdx.x * 256 + threadIdx.x; i < count; i += stride) {
        int a = g_list[i];
        int gg = grp[a];
        float soft = out_soft[a] / g_denom[gg];
        out_soft[a] = soft;
        unsigned snb = __float_as_uint(__fmaf_rn(EPS_NOISE, ue[a], soft));
        atomicMax(&g_snpack[gg], (((unsigned long long)snb) << 32) | (unsigned)a);
    }
}

// Fixup B: scatter winner's 1s. Fixed slots (2/tile, -1 = empty) + fallback list.
__global__ __launch_bounds__(256) void k_scatter(
    float* __restrict__ out_st, float* __restrict__ out_hot, int nblocks)
{
    cudaGridDependencySynchronize();
    unsigned stride = gridDim.x * 256;
    unsigned tid0 = blockIdx.x * 256 + threadIdx.x;
    unsigned nslots = 2u * (unsigned)nblocks;
    for (unsigned i = tid0; i < nslots; i += stride) {
        int gg = g_bg[i];
        if (gg >= 0) {
            unsigned long long p = g_snpack[gg];
            if (p) {
                unsigned idx = (unsigned)(p & 0xffffffffu);
                out_st[idx]  = 1.0f;
                out_hot[idx] = 1.0f;
            }
        }
    }
    unsigned nf = g_nbgf;
    for (unsigned i = tid0; i < nf; i += stride) {
        int gg = g_bgf[i];
        unsigned long long p = g_snpack[gg];
        if (p) {
            unsigned idx = (unsigned)(p & 0xffffffffu);
            out_st[idx]  = 1.0f;
            out_hot[idx] = 1.0f;
        }
    }
}

extern "C" void kernel_launch(void* const* d_in, const int* in_sizes, int n_in,
                              void* d_out, int out_size)
{
    const float* logits = (const float*)d_in[0];
    const int*   groups = (const int*)d_in[1];
    const float* u_gum;
    const float* u_eps;
    if (n_in >= 5) { u_gum = (const float*)d_in[3]; u_eps = (const float*)d_in[4]; }
    else           { u_gum = (const float*)d_in[2]; u_eps = (const float*)d_in[3]; }
    int E = in_sizes[0];

    float* out      = (float*)d_out;
    float* out_st   = out;
    float* out_hot  = out + (size_t)E;
    float* out_soft = out + 2 * (size_t)E;

    int nblocks = (E + TILE - 1) / TILE;
    int iblocks = (nblocks + 127) / 128;

    k_init<<<iblocks, 128>>>(groups, E, nblocks);

    cudaLaunchAttribute pdl[1];
    pdl[0].id = cudaLaunchAttributeProgrammaticStreamSerialization;
    pdl[0].val.programmaticStreamSerializationAllowed = 1;

    {
        cudaLaunchConfig_t cfg = {};
        cfg.gridDim = dim3(nblocks); cfg.blockDim = dim3(BLOCK);
        cfg.attrs = pdl; cfg.numAttrs = 1;
        cudaLaunchKernelEx(&cfg, k_fused, logits, u_gum, u_eps, groups,
                           out_soft, out_st, out_hot, E);
    }
    {
        cudaLaunchConfig_t cfg = {};
        cfg.gridDim = dim3(592); cfg.blockDim = dim3(256);
        cfg.attrs = pdl; cfg.numAttrs = 1;
        cudaLaunchKernelEx(&cfg, k_fix_max, u_eps, groups, out_soft);
    }
    {
        cudaLaunchConfig_t cfg = {};
        cfg.gridDim = dim3(592); cfg.blockDim = dim3(256);
        cfg.attrs = pdl; cfg.numAttrs = 1;
        cudaLaunchKernelEx(&cfg, k_scatter, out_st, out_hot, nblocks);
    }
}

// round 13
// speedup vs baseline: 1.0740x; 1.0740x over previous
#include <cuda_runtime.h>
#include <stdint.h>

#define NGMAX    (1 << 20)       // >= n_groups
#define LISTMAX  (1 << 25)       // deferred-element index list
#define NBLK_MAX 65536
#define BGFMAX   (1 << 22)       // fallback boundary-group list
#define BLOCK    256
#define EPT      8
#define TILE     (BLOCK * EPT)   // 2048
#define TABLE    768             // group-id span per tile (expected ~102)

__device__ float              g_denom[NGMAX];      // boundary groups: sum of exp(s)
__device__ unsigned long long g_snpack[NGMAX];     // boundary groups: (sn_bits<<32)|idx
__device__ unsigned g_ndef;                        // deferred element count (k_fused only)
__device__ int      g_list[LISTMAX];               // deferred element indices
__device__ int      g_bg[2 * NBLK_MAX];            // fixed slots: 2 per tile, -1 = empty
__device__ unsigned g_nbgf;                        // fallback group count (k_fused only)
__device__ int      g_bgf[BGFMAX];                 // fallback group ids

#define INV_T     (1.0f / 0.6f)
#define EPS_NOISE 1e-4f

// -log(u) for u in (0,1): near u=1, log1p poly on exact v=u-1 (Sterbenz);
// else fast __logf (rel err fine away from 1).
__device__ __forceinline__ float fast_nlog(float u) {
    float v = u - 1.0f;              // exact for u in [0.5, 1]
    if (v > -0.0703125f) {
        // log1p(v) = v*(1 - v/2 + v^2/3 - v^3/4 + v^4/5), |v| <= 0.0703
        float p = __fmaf_rn(v, 0.2f, -0.25f);
        p = __fmaf_rn(p, v, 1.0f / 3.0f);
        p = __fmaf_rn(p, v, -0.5f);
        p = __fmaf_rn(p, v, 1.0f);
        return -v * p;
    }
    return -__logf(u);
}

// exp((logit + gumbel)/T), no max-shift needed: s in [-14, 33] -> no fp32 overflow.
__device__ __forceinline__ float gumbel_e(float l, float u) {
    float y = fast_nlog(u);
    return __expf((l - __logf(y)) * INV_T);
}

// One thread per tile. No racing counters: boundary groups -> fixed slots.
__global__ __launch_bounds__(128) void k_init(const int* __restrict__ grp,
                                              int E, int nblocks)
{
    int b = blockIdx.x * 128 + threadIdx.x;
    if (b == 0) { g_ndef = 0u; g_nbgf = 0u; }
    if (b >= nblocks) return;
    int base0 = b * TILE;
    int tile_n = min(TILE, E - base0);
    int g0 = grp[base0];
    int glast = grp[base0 + tile_n - 1];
    int gprev = (base0 > 0) ? grp[base0 - 1] : -1;
    int gnext = (base0 + tile_n < E) ? grp[base0 + tile_n] : -1;
    bool g0_b = (gprev == g0);
    bool gl_b = (gnext == glast);
    if (g0 == glast) { bool any = g0_b || gl_b; g0_b = any; gl_b = any; }

    g_denom[g0] = 0.0f;    g_snpack[g0] = 0ull;
    g_denom[glast] = 0.0f; g_snpack[glast] = 0ull;

    if (glast - g0 >= TABLE) {  // pathological fallback tile: zero whole span
        for (int g = g0 + 1; g < glast; g++) { g_denom[g] = 0.0f; g_snpack[g] = 0ull; }
        g_bg[2 * b]     = -1;
        g_bg[2 * b + 1] = -1;
        return;
    }
    g_bg[2 * b]     = g0_b ? g0 : -1;
    g_bg[2 * b + 1] = (gl_b && glast != g0) ? glast : -1;
}

__global__ __launch_bounds__(BLOCK) void k_fused(
    const float* __restrict__ logits, const float* __restrict__ ug,
    const float* __restrict__ ue, const int* __restrict__ grp,
    float* __restrict__ out_soft, float* __restrict__ out_st,
    float* __restrict__ out_hot, int E)
{
    __shared__ float    s_sum[TABLE];
    __shared__ unsigned s_max[TABLE];
    __shared__ int sh[4];  // g0, glast, gprev, gnext

    const int b      = blockIdx.x;
    const int base0  = b * TILE;
    const int tid    = threadIdx.x;
    const int tile_n = min(TILE, E - base0);

    // Merged front barrier: tid0 fetches edges while all threads zero the table.
    if (tid == 0) {
        sh[0] = grp[base0];
        sh[1] = grp[base0 + tile_n - 1];
        sh[2] = (base0 > 0) ? grp[base0 - 1] : -1;
        sh[3] = (base0 + tile_n < E) ? grp[base0 + tile_n] : -1;
    }
#pragma unroll
    for (int i = tid; i < TABLE; i += BLOCK) { s_sum[i] = 0.0f; s_max[i] = 0u; }
    __syncthreads();

    const int g0    = sh[0];
    const int glast = sh[1];
    const int span  = glast - g0;
    const bool fallback = (span >= TABLE);
    bool g0_b = (sh[2] == g0);
    bool gl_b = (sh[3] == glast);
    if (g0 == glast) { bool any = g0_b || gl_b; g0_b = any; gl_b = any; }

    const int base = base0 + tid * EPT;
    const int cnt  = max(0, min(EPT, E - base));

    float e[EPT];
    int g[EPT];

    // Phase A: load logits/ug/grp only; compute e; l,u die immediately.
    if (cnt == EPT) {
        float4 L0 = __ldcs(reinterpret_cast<const float4*>(logits + base));
        float4 L1 = __ldcs(reinterpret_cast<const float4*>(logits + base) + 1);
        float4 U0 = __ldcs(reinterpret_cast<const float4*>(ug + base));
        float4 U1 = __ldcs(reinterpret_cast<const float4*>(ug + base) + 1);
        int4   G0 = __ldcs(reinterpret_cast<const int4*>(grp + base));
        int4   G1 = __ldcs(reinterpret_cast<const int4*>(grp + base) + 1);
        g[0]=G0.x;g[1]=G0.y;g[2]=G0.z;g[3]=G0.w;g[4]=G1.x;g[5]=G1.y;g[6]=G1.z;g[7]=G1.w;
        e[0]=gumbel_e(L0.x,U0.x); e[1]=gumbel_e(L0.y,U0.y);
        e[2]=gumbel_e(L0.z,U0.z); e[3]=gumbel_e(L0.w,U0.w);
        e[4]=gumbel_e(L1.x,U1.x); e[5]=gumbel_e(L1.y,U1.y);
        e[6]=gumbel_e(L1.z,U1.z); e[7]=gumbel_e(L1.w,U1.w);
    } else {
        for (int j = 0; j < cnt; j++) {
            e[j] = gumbel_e(logits[base+j], ug[base+j]);
            g[j] = grp[base+j];
        }
    }

    // Segment sums (run-aggregated; groups sorted).
    if (cnt > 0) {
        float acc = e[0]; int cg = g[0];
        for (int j = 1; j < cnt; j++) {
            if (g[j] == cg) acc += e[j];
            else {
                if (!fallback) atomicAdd(&s_sum[cg - g0], acc);
                else           atomicAdd(&g_denom[cg], acc);
                cg = g[j]; acc = e[j];
            }
        }
        if (!fallback) atomicAdd(&s_sum[cg - g0], acc);
        else           atomicAdd(&g_denom[cg], acc);
    }

    // Deferred (boundary / fallback) elements -> element index list.
    bool def[EPT];
#pragma unroll
    for (int j = 0; j < EPT; j++) {
        def[j] = (j < cnt) &&
                 (fallback || (g[j] == g0 && g0_b) || (g[j] == glast && gl_b));
    }
    {
        int nd = 0; int didx[EPT];
#pragma unroll
        for (int j = 0; j < EPT; j++)
            if (def[j]) didx[nd++] = base + j;
        if (nd) {
            unsigned p = atomicAdd(&g_ndef, (unsigned)nd);
            for (int i = 0; i < nd; i++) g_list[p + i] = didx[i];
        }
    }

    if (fallback) {
        if (tid == 0) {
            unsigned p = atomicAdd(&g_nbgf, (unsigned)(span + 1));
            for (int gg = g0; gg <= glast; gg++) g_bgf[p++] = gg;
        }
        // Stash e into out_soft (fixup converts to soft) and zero st/hot.
        if (cnt == EPT) {
            __stcs(reinterpret_cast<float4*>(out_soft + base),
                   make_float4(e[0],e[1],e[2],e[3]));
            __stcs(reinterpret_cast<float4*>(out_soft + base) + 1,
                   make_float4(e[4],e[5],e[6],e[7]));
            float4 z = make_float4(0.f,0.f,0.f,0.f);
            __stcs(reinterpret_cast<float4*>(out_st + base), z);
            __stcs(reinterpret_cast<float4*>(out_st + base) + 1, z);
            __stcs(reinterpret_cast<float4*>(out_hot + base), z);
            __stcs(reinterpret_cast<float4*>(out_hot + base) + 1, z);
        } else {
            for (int j = 0; j < cnt; j++) {
                out_soft[base + j] = e[j];
                out_st[base + j] = 0.f; out_hot[base + j] = 0.f;
            }
        }
        return;
    }

    // Prefetch ue BEFORE the barrier: its latency drains during the sync wait.
    float n[EPT];
    if (cnt == EPT) {
        float4 N0 = __ldcs(reinterpret_cast<const float4*>(ue + base));
        float4 N1 = __ldcs(reinterpret_cast<const float4*>(ue + base) + 1);
        n[0]=N0.x;n[1]=N0.y;n[2]=N0.z;n[3]=N0.w;
        n[4]=N1.x;n[5]=N1.y;n[6]=N1.z;n[7]=N1.w;
    } else {
        for (int j = 0; j < cnt; j++) n[j] = ue[base + j];
    }
    __syncthreads();

    if (tid == 0) {
        if (g0_b)                atomicAdd(&g_denom[g0],    s_sum[0]);
        if (gl_b && glast != g0) atomicAdd(&g_denom[glast], s_sum[span]);
    }

    // Phase B: soft (one reciprocal per run), written in place over e[]
    // (deferred slots keep e stashed for fixup); smem argmax for interior.
    unsigned snb[EPT];
    if (cnt > 0) {
        int cg = g[0];
        float rdn = 1.0f / s_sum[cg - g0];
#pragma unroll
        for (int j = 0; j < EPT; j++) {
            if (j < cnt) {
                if (g[j] != cg) { cg = g[j]; rdn = 1.0f / s_sum[cg - g0]; }
                float soft = e[j] * rdn;
                snb[j] = __float_as_uint(__fmaf_rn(EPS_NOISE, n[j], soft));
                if (!def[j]) e[j] = soft;  // else keep e for fixup
            }
        }
        if (cnt == EPT) {
            __stcs(reinterpret_cast<float4*>(out_soft + base),
                   make_float4(e[0],e[1],e[2],e[3]));
            __stcs(reinterpret_cast<float4*>(out_soft + base) + 1,
                   make_float4(e[4],e[5],e[6],e[7]));
        } else {
            for (int j = 0; j < cnt; j++) out_soft[base + j] = e[j];
        }
        unsigned m = 0; int cg2 = -1;
        for (int j = 0; j < cnt; j++) {
            if (def[j]) continue;
            if (g[j] == cg2) { if (snb[j] > m) m = snb[j]; }
            else {
                if (cg2 >= 0) atomicMax(&s_max[cg2 - g0], m);
                cg2 = g[j]; m = snb[j];
            }
        }
        if (cg2 >= 0) atomicMax(&s_max[cg2 - g0], m);
    }
    __syncthreads();

    // Final phase: h (def slots 0; scatter writes winners), write st/hot.
    if (cnt > 0) {
        float h[EPT];
#pragma unroll
        for (int j = 0; j < EPT; j++) {
            if (j < cnt)
                h[j] = (!def[j] && snb[j] == s_max[g[j] - g0]) ? 1.0f : 0.0f;
        }
        if (cnt == EPT) {
            __stcs(reinterpret_cast<float4*>(out_st + base),
                   make_float4(h[0],h[1],h[2],h[3]));
            __stcs(reinterpret_cast<float4*>(out_st + base) + 1,
                   make_float4(h[4],h[5],h[6],h[7]));
            __stcs(reinterpret_cast<float4*>(out_hot + base),
                   make_float4(h[0],h[1],h[2],h[3]));
            __stcs(reinterpret_cast<float4*>(out_hot + base) + 1,
                   make_float4(h[4],h[5],h[6],h[7]));
        } else {
            for (int j = 0; j < cnt; j++) {
                out_st[base + j]  = h[j];
                out_hot[base + j] = h[j];
            }
        }
    }
}

// Fixup A: per deferred element — e stashed in out_soft; finalize soft + argmax.
__global__ __launch_bounds__(256) void k_fix_max(
    const float* __restrict__ ue, const int* __restrict__ grp,
    float* __restrict__ out_soft)
{
    unsigned count = g_ndef;
    unsigned stride = gridDim.x * 256;
    for (unsigned i = blockIdx.x * 256 + threadIdx.x; i < count; i += stride) {
        int a = g_list[i];
        int gg = grp[a];
        float soft = out_soft[a] / g_denom[gg];
        out_soft[a] = soft;
        unsigned snb = __float_as_uint(__fmaf_rn(EPS_NOISE, ue[a], soft));
        atomicMax(&g_snpack[gg], (((unsigned long long)snb) << 32) | (unsigned)a);
    }
}

// Fixup B: scatter winner's 1s. Fixed slots (2/tile, -1 = empty) + fallback list.
__global__ __launch_bounds__(256) void k_scatter(
    float* __restrict__ out_st, float* __restrict__ out_hot, int nblocks)
{
    unsigned stride = gridDim.x * 256;
    unsigned tid0 = blockIdx.x * 256 + threadIdx.x;
    unsigned nslots = 2u * (unsigned)nblocks;
    for (unsigned i = tid0; i < nslots; i += stride) {
        int gg = g_bg[i];
        if (gg >= 0) {
            unsigned long long p = g_snpack[gg];
            if (p) {
                unsigned idx = (unsigned)(p & 0xffffffffu);
                out_st[idx]  = 1.0f;
                out_hot[idx] = 1.0f;
            }
        }
    }
    unsigned nf = g_nbgf;
    for (unsigned i = tid0; i < nf; i += stride) {
        int gg = g_bgf[i];
        unsigned long long p = g_snpack[gg];
        if (p) {
            unsigned idx = (unsigned)(p & 0xffffffffu);
            out_st[idx]  = 1.0f;
            out_hot[idx] = 1.0f;
        }
    }
}

extern "C" void kernel_launch(void* const* d_in, const int* in_sizes, int n_in,
                              void* d_out, int out_size)
{
    const float* logits = (const float*)d_in[0];
    const int*   groups = (const int*)d_in[1];
    const float* u_gum;
    const float* u_eps;
    if (n_in >= 5) { u_gum = (const float*)d_in[3]; u_eps = (const float*)d_in[4]; }
    else           { u_gum = (const float*)d_in[2]; u_eps = (const float*)d_in[3]; }
    int E = in_sizes[0];

    float* out      = (float*)d_out;
    float* out_st   = out;
    float* out_hot  = out + (size_t)E;
    float* out_soft = out + 2 * (size_t)E;

    int nblocks = (E + TILE - 1) / TILE;
    int iblocks = (nblocks + 127) / 128;

    k_init<<<iblocks, 128>>>(groups, E, nblocks);
    k_fused<<<nblocks, BLOCK>>>(logits, u_gum, u_eps, groups,
                                out_soft, out_st, out_hot, E);
    k_fix_max<<<592, 256>>>(u_eps, groups, out_soft);
    k_scatter<<<592, 256>>>(out_st, out_hot, nblocks);
}

// round 15
// speedup vs baseline: 1.0766x; 1.0024x over previous
#include <cuda_runtime.h>
#include <stdint.h>

#define NGMAX    (1 << 20)       // >= n_groups
#define LISTMAX  (1 << 25)       // deferred-element index list
#define NBLK_MAX 65536
#define BGFMAX   (1 << 22)       // fallback boundary-group list
#define BLOCK    256
#define EPT      8
#define TILE     (BLOCK * EPT)   // 2048
#define TABLE    768             // group-id span per tile (expected ~102)

__device__ float              g_denom[NGMAX];      // boundary groups: sum of exp(s)
__device__ unsigned long long g_snpack[NGMAX];     // boundary groups: (sn_bits<<32)|idx
__device__ unsigned g_ndef;                        // deferred element count (k_fused only)
__device__ int      g_list[LISTMAX];               // deferred element indices
__device__ int      g_bg[2 * NBLK_MAX];            // fixed slots: 2 per tile, -1 = empty
__device__ unsigned g_nbgf;                        // fallback group count (k_fused only)
__device__ int      g_bgf[BGFMAX];                 // fallback group ids

#define INV_T     (1.0f / 0.6f)
#define EPS_NOISE 1e-4f

// -log(u) for u in (0,1): near u=1, log1p poly on exact v=u-1 (Sterbenz);
// else fast __logf (rel err fine away from 1). R13-exact numerics:
// argmax tie-flips vs reference demand soft accuracy ~1e-6 (R14 lesson).
__device__ __forceinline__ float fast_nlog(float u) {
    float v = u - 1.0f;              // exact for u in [0.5, 1]
    if (v > -0.0703125f) {
        // log1p(v) = v*(1 - v/2 + v^2/3 - v^3/4 + v^4/5), |v| <= 0.0703
        float p = __fmaf_rn(v, 0.2f, -0.25f);
        p = __fmaf_rn(p, v, 1.0f / 3.0f);
        p = __fmaf_rn(p, v, -0.5f);
        p = __fmaf_rn(p, v, 1.0f);
        return -v * p;
    }
    return -__logf(u);
}

// exp((logit + gumbel)/T), no max-shift needed: s in [-14, 33] -> no fp32 overflow.
__device__ __forceinline__ float gumbel_e(float l, float u) {
    float y = fast_nlog(u);
    return __expf((l - __logf(y)) * INV_T);
}

// One thread per tile. No racing counters: boundary groups -> fixed slots.
__global__ __launch_bounds__(128) void k_init(const int* __restrict__ grp,
                                              int E, int nblocks)
{
    int b = blockIdx.x * 128 + threadIdx.x;
    if (b == 0) { g_ndef = 0u; g_nbgf = 0u; }
    if (b >= nblocks) return;
    int base0 = b * TILE;
    int tile_n = min(TILE, E - base0);
    int g0 = grp[base0];
    int glast = grp[base0 + tile_n - 1];
    int gprev = (base0 > 0) ? grp[base0 - 1] : -1;
    int gnext = (base0 + tile_n < E) ? grp[base0 + tile_n] : -1;
    bool g0_b = (gprev == g0);
    bool gl_b = (gnext == glast);
    if (g0 == glast) { bool any = g0_b || gl_b; g0_b = any; gl_b = any; }

    g_denom[g0] = 0.0f;    g_snpack[g0] = 0ull;
    g_denom[glast] = 0.0f; g_snpack[glast] = 0ull;

    if (glast - g0 >= TABLE) {  // pathological fallback tile: zero whole span
        for (int g = g0 + 1; g < glast; g++) { g_denom[g] = 0.0f; g_snpack[g] = 0ull; }
        g_bg[2 * b]     = -1;
        g_bg[2 * b + 1] = -1;
        return;
    }
    g_bg[2 * b]     = g0_b ? g0 : -1;
    g_bg[2 * b + 1] = (gl_b && glast != g0) ? glast : -1;
}

__global__ __launch_bounds__(BLOCK) void k_fused(
    const float* __restrict__ logits, const float* __restrict__ ug,
    const float* __restrict__ ue, const int* __restrict__ grp,
    float* __restrict__ out_soft, float* __restrict__ out_st,
    float* __restrict__ out_hot, int E)
{
    __shared__ float    s_sum[TABLE];
    __shared__ unsigned s_max[TABLE];
    __shared__ int sh[4];  // g0, glast, gprev, gnext

    const int b      = blockIdx.x;
    const int base0  = b * TILE;
    const int tid    = threadIdx.x;
    const int tile_n = min(TILE, E - base0);

    // Merged front barrier: tid0 fetches edges while all threads zero the table.
    if (tid == 0) {
        sh[0] = grp[base0];
        sh[1] = grp[base0 + tile_n - 1];
        sh[2] = (base0 > 0) ? grp[base0 - 1] : -1;
        sh[3] = (base0 + tile_n < E) ? grp[base0 + tile_n] : -1;
    }
#pragma unroll
    for (int i = tid; i < TABLE; i += BLOCK) { s_sum[i] = 0.0f; s_max[i] = 0u; }
    __syncthreads();

    const int g0    = sh[0];
    const int glast = sh[1];
    const int span  = glast - g0;
    const bool fallback = (span >= TABLE);
    bool g0_b = (sh[2] == g0);
    bool gl_b = (sh[3] == glast);
    if (g0 == glast) { bool any = g0_b || gl_b; g0_b = any; gl_b = any; }

    const int base = base0 + tid * EPT;
    const int cnt  = max(0, min(EPT, E - base));

    float e[EPT];
    int g[EPT];

    // Phase A: load logits/ug/grp only; compute e; l,u die immediately.
    if (cnt == EPT) {
        float4 L0 = __ldcs(reinterpret_cast<const float4*>(logits + base));
        float4 L1 = __ldcs(reinterpret_cast<const float4*>(logits + base) + 1);
        float4 U0 = __ldcs(reinterpret_cast<const float4*>(ug + base));
        float4 U1 = __ldcs(reinterpret_cast<const float4*>(ug + base) + 1);
        int4   G0 = __ldcs(reinterpret_cast<const int4*>(grp + base));
        int4   G1 = __ldcs(reinterpret_cast<const int4*>(grp + base) + 1);
        g[0]=G0.x;g[1]=G0.y;g[2]=G0.z;g[3]=G0.w;g[4]=G1.x;g[5]=G1.y;g[6]=G1.z;g[7]=G1.w;
        e[0]=gumbel_e(L0.x,U0.x); e[1]=gumbel_e(L0.y,U0.y);
        e[2]=gumbel_e(L0.z,U0.z); e[3]=gumbel_e(L0.w,U0.w);
        e[4]=gumbel_e(L1.x,U1.x); e[5]=gumbel_e(L1.y,U1.y);
        e[6]=gumbel_e(L1.z,U1.z); e[7]=gumbel_e(L1.w,U1.w);
    } else {
        for (int j = 0; j < cnt; j++) {
            e[j] = gumbel_e(logits[base+j], ug[base+j]);
            g[j] = grp[base+j];
        }
    }

    // Segment sums (run-aggregated; groups sorted).
    if (cnt > 0) {
        float acc = e[0]; int cg = g[0];
        for (int j = 1; j < cnt; j++) {
            if (g[j] == cg) acc += e[j];
            else {
                if (!fallback) atomicAdd(&s_sum[cg - g0], acc);
                else           atomicAdd(&g_denom[cg], acc);
                cg = g[j]; acc = e[j];
            }
        }
        if (!fallback) atomicAdd(&s_sum[cg - g0], acc);
        else           atomicAdd(&g_denom[cg], acc);
    }

    // Deferred (boundary / fallback) elements -> element index list.
    bool def[EPT];
#pragma unroll
    for (int j = 0; j < EPT; j++) {
        def[j] = (j < cnt) &&
                 (fallback || (g[j] == g0 && g0_b) || (g[j] == glast && gl_b));
    }
    {
        int nd = 0; int didx[EPT];
#pragma unroll
        for (int j = 0; j < EPT; j++)
            if (def[j]) didx[nd++] = base + j;
        if (nd) {
            unsigned p = atomicAdd(&g_ndef, (unsigned)nd);
            for (int i = 0; i < nd; i++) g_list[p + i] = didx[i];
        }
    }

    if (fallback) {
        if (tid == 0) {
            unsigned p = atomicAdd(&g_nbgf, (unsigned)(span + 1));
            for (int gg = g0; gg <= glast; gg++) g_bgf[p++] = gg;
        }
        // Stash e into out_soft (fixup converts to soft) and zero st/hot.
        if (cnt == EPT) {
            __stcs(reinterpret_cast<float4*>(out_soft + base),
                   make_float4(e[0],e[1],e[2],e[3]));
            __stcs(reinterpret_cast<float4*>(out_soft + base) + 1,
                   make_float4(e[4],e[5],e[6],e[7]));
            float4 z = make_float4(0.f,0.f,0.f,0.f);
            __stcs(reinterpret_cast<float4*>(out_st + base), z);
            __stcs(reinterpret_cast<float4*>(out_st + base) + 1, z);
            __stcs(reinterpret_cast<float4*>(out_hot + base), z);
            __stcs(reinterpret_cast<float4*>(out_hot + base) + 1, z);
        } else {
            for (int j = 0; j < cnt; j++) {
                out_soft[base + j] = e[j];
                out_st[base + j] = 0.f; out_hot[base + j] = 0.f;
            }
        }
        return;
    }

    // Prefetch ue BEFORE the barrier: its latency drains during the sync wait.
    float n[EPT];
    if (cnt == EPT) {
        float4 N0 = __ldcs(reinterpret_cast<const float4*>(ue + base));
        float4 N1 = __ldcs(reinterpret_cast<const float4*>(ue + base) + 1);
        n[0]=N0.x;n[1]=N0.y;n[2]=N0.z;n[3]=N0.w;
        n[4]=N1.x;n[5]=N1.y;n[6]=N1.z;n[7]=N1.w;
    } else {
        for (int j = 0; j < cnt; j++) n[j] = ue[base + j];
    }
    __syncthreads();

    if (tid == 0) {
        if (g0_b)                atomicAdd(&g_denom[g0],    s_sum[0]);
        if (gl_b && glast != g0) atomicAdd(&g_denom[glast], s_sum[span]);
    }

    // Phase B: soft (one reciprocal per run), written in place over e[]
    // (deferred slots keep e stashed for fixup); smem argmax for interior.
    unsigned snb[EPT];
    if (cnt > 0) {
        int cg = g[0];
        float rdn = 1.0f / s_sum[cg - g0];
#pragma unroll
        for (int j = 0; j < EPT; j++) {
            if (j < cnt) {
                if (g[j] != cg) { cg = g[j]; rdn = 1.0f / s_sum[cg - g0]; }
                float soft = e[j] * rdn;
                snb[j] = __float_as_uint(__fmaf_rn(EPS_NOISE, n[j], soft));
                if (!def[j]) e[j] = soft;  // else keep e for fixup
            }
        }
        if (cnt == EPT) {
            __stcs(reinterpret_cast<float4*>(out_soft + base),
                   make_float4(e[0],e[1],e[2],e[3]));
            __stcs(reinterpret_cast<float4*>(out_soft + base) + 1,
                   make_float4(e[4],e[5],e[6],e[7]));
        } else {
            for (int j = 0; j < cnt; j++) out_soft[base + j] = e[j];
        }
        unsigned m = 0; int cg2 = -1;
        for (int j = 0; j < cnt; j++) {
            if (def[j]) continue;
            if (g[j] == cg2) { if (snb[j] > m) m = snb[j]; }
            else {
                if (cg2 >= 0) atomicMax(&s_max[cg2 - g0], m);
                cg2 = g[j]; m = snb[j];
            }
        }
        if (cg2 >= 0) atomicMax(&s_max[cg2 - g0], m);
    }
    __syncthreads();

    // Final phase: h (def slots 0; scatter writes winners), write st/hot.
    if (cnt > 0) {
        float h[EPT];
#pragma unroll
        for (int j = 0; j < EPT; j++) {
            if (j < cnt)
                h[j] = (!def[j] && snb[j] == s_max[g[j] - g0]) ? 1.0f : 0.0f;
        }
        if (cnt == EPT) {
            __stcs(reinterpret_cast<float4*>(out_st + base),
                   make_float4(h[0],h[1],h[2],h[3]));
            __stcs(reinterpret_cast<float4*>(out_st + base) + 1,
                   make_float4(h[4],h[5],h[6],h[7]));
            __stcs(reinterpret_cast<float4*>(out_hot + base),
                   make_float4(h[0],h[1],h[2],h[3]));
            __stcs(reinterpret_cast<float4*>(out_hot + base) + 1,
                   make_float4(h[4],h[5],h[6],h[7]));
        } else {
            for (int j = 0; j < cnt; j++) {
                out_st[base + j]  = h[j];
                out_hot[base + j] = h[j];
            }
        }
    }
}

// Fixup A: per deferred element — e stashed in out_soft; finalize soft + argmax.
__global__ __launch_bounds__(256) void k_fix_max(
    const float* __restrict__ ue, const int* __restrict__ grp,
    float* __restrict__ out_soft)
{
    unsigned count = g_ndef;
    unsigned stride = gridDim.x * 256;
    for (unsigned i = blockIdx.x * 256 + threadIdx.x; i < count; i += stride) {
        int a = g_list[i];
        int gg = grp[a];
        float soft = out_soft[a] / g_denom[gg];
        out_soft[a] = soft;
        unsigned snb = __float_as_uint(__fmaf_rn(EPS_NOISE, ue[a], soft));
        atomicMax(&g_snpack[gg], (((unsigned long long)snb) << 32) | (unsigned)a);
    }
}

// Fixup B: scatter winner's 1s. Fixed slots (2/tile, -1 = empty) + fallback list.
__global__ __launch_bounds__(256) void k_scatter(
    float* __restrict__ out_st, float* __restrict__ out_hot, int nblocks)
{
    unsigned stride = gridDim.x * 256;
    unsigned tid0 = blockIdx.x * 256 + threadIdx.x;
    unsigned nslots = 2u * (unsigned)nblocks;
    for (unsigned i = tid0; i < nslots; i += stride) {
        int gg = g_bg[i];
        if (gg >= 0) {
            unsigned long long p = g_snpack[gg];
            if (p) {
                unsigned idx = (unsigned)(p & 0xffffffffu);
                out_st[idx]  = 1.0f;
                out_hot[idx] = 1.0f;
            }
        }
    }
    unsigned nf = g_nbgf;
    for (unsigned i = tid0; i < nf; i += stride) {
        int gg = g_bgf[i];
        unsigned long long p = g_snpack[gg];
        if (p) {
            unsigned idx = (unsigned)(p & 0xffffffffu);
            out_st[idx]  = 1.0f;
            out_hot[idx] = 1.0f;
        }
    }
}

extern "C" void kernel_launch(void* const* d_in, const int* in_sizes, int n_in,
                              void* d_out, int out_size)
{
    const float* logits = (const float*)d_in[0];
    const int*   groups = (const int*)d_in[1];
    const float* u_gum;
    const float* u_eps;
    if (n_in >= 5) { u_gum = (const float*)d_in[3]; u_eps = (const float*)d_in[4]; }
    else           { u_gum = (const float*)d_in[2]; u_eps = (const float*)d_in[3]; }
    int E = in_sizes[0];

    float* out      = (float*)d_out;
    float* out_st   = out;
    float* out_hot  = out + (size_t)E;
    float* out_soft = out + 2 * (size_t)E;

    int nblocks = (E + TILE - 1) / TILE;
    int iblocks = (nblocks + 127) / 128;

    k_init<<<iblocks, 128>>>(groups, E, nblocks);
    k_fused<<<nblocks, BLOCK>>>(logits, u_gum, u_eps, groups,
                                out_soft, out_st, out_hot, E);
    k_fix_max<<<1184, 256>>>(u_eps, groups, out_soft);
    k_scatter<<<1184, 256>>>(out_st, out_hot, nblocks);
}